// round 8
// baseline (speedup 1.0000x reference)
#include <cuda_runtime.h>
#include <math.h>

#define NMAX 100000
#define EMAX 1600000
#define HEADS 4
#define HID 32
#define F1 128
#define IN_NODE 12
#define IN_GLB 11
#define IN1 23
#define EDGE_DIM 5
#define DEC_IN 69
#define DEC_H1 64
#define DEC_H2 32
#define DEC_OUT 4

__device__ float g_g[NMAX * F1];
__device__ float g_h1[NMAX * F1];
__device__ float g_h2[NMAX * HID];
__device__ float g_pa[NMAX * DEC_H1];
__device__ float g_pb[NMAX * DEC_H1];
__device__ __align__(16) float g_als[NMAX * HEADS];
__device__ __align__(16) float g_ald[NMAX * HEADS];
__device__ int   g_cnt[NMAX];
__device__ int   g_off[NMAX + 1];
__device__ int   g_cur[NMAX];
__device__ int   g_srcs[EMAX];
__device__ int   g_bsum[128];
__device__ float g_t1[F1];
__device__ float g_w1tt[IN_NODE * F1];
__device__ float g_w2t[DEC_H1 * DEC_H2];

__device__ __forceinline__ float lrelu02(float x) { return x > 0.f ? x : 0.2f * x; }
__device__ __forceinline__ float eluf(float x)    { return x > 0.f ? x : expm1f(x); }

// ---- packed f32x2 helpers ---------------------------------------------------
__device__ __forceinline__ unsigned long long pk2(float lo, float hi) {
    unsigned long long r;
    asm("mov.b64 %0, {%1, %2};" : "=l"(r) : "f"(lo), "f"(hi));
    return r;
}
__device__ __forceinline__ void fma2(unsigned long long& d, unsigned long long a,
                                     unsigned long long b) {
    asm("fma.rn.f32x2 %0, %1, %2, %0;" : "+l"(d) : "l"(a), "l"(b));
}
__device__ __forceinline__ float2 upk2(unsigned long long v) {
    float2 f;
    asm("mov.b64 {%0, %1}, %2;" : "=f"(f.x), "=f"(f.y) : "l"(v));
    return f;
}

// ---------------- prep ------------------------------------------------------
__global__ void k_prep(const float* __restrict__ u, const float* __restrict__ W1,
                       const float* __restrict__ dw2) {
    int tid = threadIdx.x;
    if (tid < F1) {
        float s = 0.f;
        #pragma unroll
        for (int k = 0; k < IN_GLB; k++) s += u[k] * W1[tid * IN1 + IN_NODE + k];
        g_t1[tid] = s;
    }
    for (int i = tid; i < IN_NODE * F1; i += blockDim.x) {
        int k = i >> 7, f = i & 127;
        g_w1tt[i] = W1[f * IN1 + k];
    }
    for (int i = tid; i < DEC_H1 * DEC_H2; i += blockDim.x) {
        int k = i >> 5, o = i & 31;
        g_w2t[i] = dw2[o * DEC_H1 + k];
    }
}

// ---------------- layer-1 node transform + attention logits ----------------
__global__ void k_gemm1(const float* __restrict__ x,
                        const float* __restrict__ asrc, const float* __restrict__ adst,
                        int N) {
    int n0 = blockIdx.x * 4;
    int f = threadIdx.x;
    __shared__ float xs[4][IN_NODE];
    if (f < 4 * IN_NODE) {
        int i = f / IN_NODE, k = f - i * IN_NODE;
        int n = n0 + i;
        xs[i][k] = (n < N) ? x[n * IN_NODE + k] : 0.f;
    }
    __syncthreads();
    float acc[4];
    float t = g_t1[f];
    #pragma unroll
    for (int i = 0; i < 4; i++) acc[i] = t;
    #pragma unroll
    for (int k = 0; k < IN_NODE; k++) {
        float w = g_w1tt[k * F1 + f];
        #pragma unroll
        for (int i = 0; i < 4; i++) acc[i] += xs[i][k] * w;
    }
    int h = f >> 5;
    float cas = asrc[f], cad = adst[f];
    #pragma unroll
    for (int i = 0; i < 4; i++) {
        int n = n0 + i;
        if (n >= N) break;
        g_g[n * F1 + f] = acc[i];
        float vs = acc[i] * cas, vd = acc[i] * cad;
        #pragma unroll
        for (int o = 16; o; o >>= 1) {
            vs += __shfl_xor_sync(0xffffffffu, vs, o);
            vd += __shfl_xor_sync(0xffffffffu, vd, o);
        }
        if ((f & 31) == 0) {
            g_als[n * HEADS + h] = vs;
            g_ald[n * HEADS + h] = vd;
        }
    }
}

// ---------------- layer-2 node transform (16 nodes/block, packed FMA) ------
#define G2N 16
__global__ __launch_bounds__(128) void k_gemm2(const float* __restrict__ W2,
                        const float* __restrict__ asrc, const float* __restrict__ adst,
                        int N) {
    int n0 = blockIdx.x * G2N;
    int f = threadIdx.x;
    __shared__ __align__(16) float hst[F1][G2N];
    #pragma unroll
    for (int i = 0; i < G2N; i++) {
        int n = n0 + i;
        hst[f][i] = (n < N) ? g_h1[n * F1 + f] : 0.f;
    }
    __syncthreads();
    unsigned long long acc2[8];
    #pragma unroll
    for (int p = 0; p < 8; p++) acc2[p] = 0ull;
    const float4* wrow = reinterpret_cast<const float4*>(W2 + f * F1);
    #pragma unroll 4
    for (int kq = 0; kq < F1 / 4; kq++) {
        float4 wv = wrow[kq];
        #pragma unroll
        for (int kk = 0; kk < 4; kk++) {
            float w = (kk == 0) ? wv.x : (kk == 1) ? wv.y : (kk == 2) ? wv.z : wv.w;
            unsigned long long ws = pk2(w, w);
            int k = kq * 4 + kk;
            const ulonglong2* hp = reinterpret_cast<const ulonglong2*>(&hst[k][0]);
            #pragma unroll
            for (int p = 0; p < 4; p++) {
                ulonglong2 hv = hp[p];
                fma2(acc2[p * 2], hv.x, ws);
                fma2(acc2[p * 2 + 1], hv.y, ws);
            }
        }
    }
    float acc[G2N];
    #pragma unroll
    for (int p = 0; p < 8; p++) {
        float2 t = upk2(acc2[p]);
        acc[p * 2] = t.x;
        acc[p * 2 + 1] = t.y;
    }
    int h = f >> 5;
    float cas = asrc[f], cad = adst[f];
    #pragma unroll
    for (int i = 0; i < G2N; i++) {
        int n = n0 + i;
        if (n >= N) break;
        g_g[n * F1 + f] = acc[i];
        float vs = acc[i] * cas, vd = acc[i] * cad;
        #pragma unroll
        for (int o = 16; o; o >>= 1) {
            vs += __shfl_xor_sync(0xffffffffu, vs, o);
            vd += __shfl_xor_sync(0xffffffffu, vd, o);
        }
        if ((f & 31) == 0) {
            g_als[n * HEADS + h] = vs;
            g_ald[n * HEADS + h] = vd;
        }
    }
}

// ---------------- CSR build --------------------------------------------------
__global__ void k_zero(int N) {
    int i = blockIdx.x * blockDim.x + threadIdx.x;
    if (i < N) g_cnt[i] = 0;
}
__global__ void k_hist(const int* __restrict__ dst, int M) {
    int e = blockIdx.x * blockDim.x + threadIdx.x;
    if (e < M) atomicAdd(&g_cnt[dst[e]], 1);
}
__global__ void k_scan1(int N) {
    __shared__ int sh[1024];
    int tid = threadIdx.x;
    int i = blockIdx.x * 1024 + tid;
    int v = (i < N) ? g_cnt[i] : 0;
    sh[tid] = v;
    __syncthreads();
    for (int o = 1; o < 1024; o <<= 1) {
        int t = (tid >= o) ? sh[tid - o] : 0;
        __syncthreads();
        sh[tid] += t;
        __syncthreads();
    }
    if (i < N) g_off[i] = sh[tid] - v;
    if (tid == 1023) g_bsum[blockIdx.x] = sh[1023];
}
__global__ void k_scan3(int nb, int N, int M) {
    __shared__ int sh[128];
    int tid = threadIdx.x;
    if (tid < 128) {
        int v = (tid < nb) ? g_bsum[tid] : 0;
        sh[tid] = v;
    }
    __syncthreads();
    if (tid < 128) {
        for (int o = 1; o < 128; o <<= 1) {
            int t = (tid >= o) ? sh[tid - o] : 0;
            __syncthreads();
            sh[tid] += t;
            __syncthreads();
        }
    } else {
        for (int o = 1; o < 128; o <<= 1) { __syncthreads(); __syncthreads(); }
    }
    int i = blockIdx.x * blockDim.x + tid;
    if (i < N) {
        int blk = i >> 10;
        int ex = (blk == 0) ? 0 : sh[blk - 1];
        int v = g_off[i] + ex;
        g_off[i] = v;
        g_cur[i] = v;
    }
    if (i == 0) g_off[N] = M;
}
__global__ void k_scatter(const int* __restrict__ src, const int* __restrict__ dst, int M) {
    int e = blockIdx.x * blockDim.x + threadIdx.x;
    if (e < M) {
        int d = dst[e];
        int p = atomicAdd(&g_cur[d], 1);
        g_srcs[p] = src[e];
    }
}

// ---------------- GAT aggregation: ONE warp per node, all 4 heads -----------
// lane layout: h = lane>>3 (head), sub = lane&7 (float4 slice of the 32-col head)
__global__ __launch_bounds__(128) void k_agg(const float* __restrict__ bias,
                                             int concat, int N) {
    int n = blockIdx.x * 4 + (threadIdx.x >> 5);
    if (n >= N) return;
    int lane = threadIdx.x & 31;
    int h = lane >> 3, sub = lane & 7;
    int beg = g_off[n], end = g_off[n + 1];

    float aldn = g_ald[n * HEADS + h];
    float ws = __expf(lrelu02(g_als[n * HEADS + h] + aldn));

    const float* grow = g_g + (h << 5) + (sub << 2);
    float4 gs = *reinterpret_cast<const float4*>(grow + (size_t)n * F1);
    float4 acc = make_float4(ws * gs.x, ws * gs.y, ws * gs.z, ws * gs.w);
    float psum = 0.f;
    int gbase = h << 3;

    for (int base = beg; base < end; base += 8) {
        int j = base + sub;
        int s = 0;
        float w = 0.f;
        if (j < end) {
            s = g_srcs[j];
            w = __expf(lrelu02(g_als[s * HEADS + h] + aldn));
            psum += w;
        }
        int lim = min(8, end - base);
        for (int kk = 0; kk < lim; kk++) {
            int sk  = __shfl_sync(0xffffffffu, s, gbase + kk);
            float wk = __shfl_sync(0xffffffffu, w, gbase + kk);
            float4 gv = *reinterpret_cast<const float4*>(grow + (size_t)sk * F1);
            acc.x += wk * gv.x;
            acc.y += wk * gv.y;
            acc.z += wk * gv.z;
            acc.w += wk * gv.w;
        }
    }
    // psum reduce within 8-lane head group
    psum += __shfl_xor_sync(0xffffffffu, psum, 1);
    psum += __shfl_xor_sync(0xffffffffu, psum, 2);
    psum += __shfl_xor_sync(0xffffffffu, psum, 4);
    float inv = 1.f / (psum + ws);
    acc.x *= inv; acc.y *= inv; acc.z *= inv; acc.w *= inv;

    if (concat) {
        float4 b = *reinterpret_cast<const float4*>(bias + (h << 5) + (sub << 2));
        float4 o;
        o.x = eluf(acc.x + b.x);
        o.y = eluf(acc.y + b.y);
        o.z = eluf(acc.z + b.z);
        o.w = eluf(acc.w + b.w);
        *reinterpret_cast<float4*>(g_h1 + (size_t)n * F1 + (h << 5) + (sub << 2)) = o;
    } else {
        // mean over heads: lanes with same sub differ in bits 3,4 (head bits)
        acc.x += __shfl_xor_sync(0xffffffffu, acc.x, 8);
        acc.y += __shfl_xor_sync(0xffffffffu, acc.y, 8);
        acc.z += __shfl_xor_sync(0xffffffffu, acc.z, 8);
        acc.w += __shfl_xor_sync(0xffffffffu, acc.w, 8);
        acc.x += __shfl_xor_sync(0xffffffffu, acc.x, 16);
        acc.y += __shfl_xor_sync(0xffffffffu, acc.y, 16);
        acc.z += __shfl_xor_sync(0xffffffffu, acc.z, 16);
        acc.w += __shfl_xor_sync(0xffffffffu, acc.w, 16);
        if (h == 0) {
            float4 b = *reinterpret_cast<const float4*>(bias + (sub << 2));
            float4 o;
            o.x = eluf(acc.x * 0.25f + b.x);
            o.y = eluf(acc.y * 0.25f + b.y);
            o.z = eluf(acc.z * 0.25f + b.z);
            o.w = eluf(acc.w * 0.25f + b.w);
            *reinterpret_cast<float4*>(g_h2 + (size_t)n * HID + (sub << 2)) = o;
        }
    }
}

// ---------------- decoder precompute: pa/pb (tiled, smem weights) -----------
__global__ __launch_bounds__(256) void k_pab(const float* __restrict__ dw1, int N) {
    __shared__ float sdw[64 * 65];
    __shared__ float sh2[16 * 32];
    int tid = threadIdx.x;
    for (int i = tid; i < 64 * 64; i += 256) {
        int o = i >> 6, k = i & 63;
        sdw[o * 65 + k] = dw1[o * DEC_IN + k];
    }
    int n0 = blockIdx.x * 16;
    for (int i = tid; i < 16 * 32; i += 256) {
        int nl = i >> 5, k = i & 31;
        int n = n0 + nl;
        sh2[i] = (n < N) ? g_h2[n * HID + k] : 0.f;
    }
    __syncthreads();
    int o = tid & 63, ng = tid >> 6;
    float pa[4] = {0.f, 0.f, 0.f, 0.f}, pb[4] = {0.f, 0.f, 0.f, 0.f};
    #pragma unroll
    for (int k = 0; k < 32; k++) {
        float wa = sdw[o * 65 + k];
        float wb = sdw[o * 65 + 32 + k];
        #pragma unroll
        for (int j = 0; j < 4; j++) {
            float hv = sh2[(ng * 4 + j) * 32 + k];
            pa[j] += wa * hv;
            pb[j] += wb * hv;
        }
    }
    #pragma unroll
    for (int j = 0; j < 4; j++) {
        int n = n0 + ng * 4 + j;
        if (n < N) {
            g_pa[n * 64 + o] = pa[j];
            g_pb[n * 64 + o] = pb[j];
        }
    }
}

// ---------------- decoder: 64-edge tiles, splat-packed GEMM2 ----------------
#define TB 64
#define ZS (TB + 4)
__global__ __launch_bounds__(256) void k_dec(
    const int* __restrict__ ei, const float* __restrict__ eattr,
    const float* __restrict__ dw1, const float* __restrict__ db1,
    const float* __restrict__ db2, const float* __restrict__ dw3,
    const float* __restrict__ db3, float* __restrict__ out, int M) {
    __shared__ __align__(16) unsigned long long sw2p[DEC_H1 * DEC_H2];
    __shared__ float sw3[DEC_H2 * DEC_OUT];
    __shared__ float sb2[DEC_H2];
    __shared__ float sb3[DEC_OUT];
    __shared__ float sw1c[EDGE_DIM * 64];
    __shared__ float sdb1[64];
    __shared__ int ssrc[TB], sdst[TB];
    __shared__ float eat[TB * EDGE_DIM];
    __shared__ __align__(16) float z1t[DEC_H1 * ZS];
    __shared__ __align__(16) float z2t[DEC_H2 * ZS];
    int tid = threadIdx.x;

    for (int i = tid; i < DEC_H1 * DEC_H2; i += 256) {
        float w = g_w2t[i];
        sw2p[i] = pk2(w, w);
    }
    if (tid < 128) sw3[tid] = dw3[tid];
    if (tid < 64)  sdb1[tid] = db1[tid];
    if (tid < 32)  sb2[tid] = db2[tid];
    if (tid < 4)   sb3[tid] = db3[tid];
    for (int i = tid; i < EDGE_DIM * 64; i += 256) {
        int k = i >> 6, o = i & 63;
        sw1c[i] = dw1[o * DEC_IN + 64 + k];
    }

    const int* srcp = ei;
    const int* dstp = ei + M;
    int ntiles = (M + TB - 1) / TB;
    int tx = tid & 15;
    int ty = tid >> 4;
    int o0 = tx * 2, e0 = ty * 4;

    for (int tile = blockIdx.x; tile < ntiles; tile += gridDim.x) {
        int eb = tile * TB;
        int nE = min(TB, M - eb);
        __syncthreads();
        if (tid < TB) {
            ssrc[tid] = (tid < nE) ? srcp[eb + tid] : 0;
            sdst[tid] = (tid < nE) ? dstp[eb + tid] : 0;
        }
        for (int i = tid; i < TB * EDGE_DIM; i += 256) {
            int gi = eb * EDGE_DIM + i;
            eat[i] = (gi < M * EDGE_DIM) ? eattr[gi] : 0.f;
        }
        __syncthreads();

        for (int i = tid; i < TB * 64; i += 256) {
            int e = i >> 6, o = i & 63;
            float v = g_pa[(size_t)ssrc[e] * 64 + o] + g_pb[(size_t)sdst[e] * 64 + o]
                      + sdb1[o];
            #pragma unroll
            for (int k = 0; k < EDGE_DIM; k++) v += sw1c[k * 64 + o] * eat[e * EDGE_DIM + k];
            z1t[o * ZS + e] = fmaxf(v, 0.f);
        }
        __syncthreads();

        unsigned long long a00 = 0ull, a01 = 0ull, a10 = 0ull, a11 = 0ull;
        #pragma unroll 8
        for (int k = 0; k < DEC_H1; k++) {
            ulonglong2 zp = *reinterpret_cast<const ulonglong2*>(&z1t[k * ZS + e0]);
            unsigned long long w0 = sw2p[k * DEC_H2 + o0];
            unsigned long long w1 = sw2p[k * DEC_H2 + o0 + 1];
            fma2(a00, zp.x, w0);
            fma2(a01, zp.x, w1);
            fma2(a10, zp.y, w0);
            fma2(a11, zp.y, w1);
        }
        {
            float b0 = sb2[o0], b1 = sb2[o0 + 1];
            float2 t00 = upk2(a00), t01 = upk2(a01), t10 = upk2(a10), t11 = upk2(a11);
            z2t[o0 * ZS + e0]           = fmaxf(t00.x + b0, 0.f);
            z2t[o0 * ZS + e0 + 1]       = fmaxf(t00.y + b0, 0.f);
            z2t[o0 * ZS + e0 + 2]       = fmaxf(t10.x + b0, 0.f);
            z2t[o0 * ZS + e0 + 3]       = fmaxf(t10.y + b0, 0.f);
            z2t[(o0 + 1) * ZS + e0]     = fmaxf(t01.x + b1, 0.f);
            z2t[(o0 + 1) * ZS + e0 + 1] = fmaxf(t01.y + b1, 0.f);
            z2t[(o0 + 1) * ZS + e0 + 2] = fmaxf(t11.x + b1, 0.f);
            z2t[(o0 + 1) * ZS + e0 + 3] = fmaxf(t11.y + b1, 0.f);
        }
        __syncthreads();

        {
            int e = tid & 63, o = tid >> 6;
            float acc = sb3[o];
            #pragma unroll
            for (int k = 0; k < DEC_H2; k++) acc += z2t[k * ZS + e] * sw3[o * DEC_H2 + k];
            if (e < nE) out[(eb + e) * DEC_OUT + o] = acc;
        }
    }
}

// ---------------- launch -----------------------------------------------------
extern "C" void kernel_launch(void* const* d_in, const int* in_sizes, int n_in,
                              void* d_out, int out_size) {
    const float* x     = (const float*)d_in[0];
    const int*   ei    = (const int*)d_in[1];
    const float* eattr = (const float*)d_in[2];
    const float* u     = (const float*)d_in[3];
    const float* W1    = (const float*)d_in[4];
    const float* as1   = (const float*)d_in[5];
    const float* ad1   = (const float*)d_in[6];
    const float* b1    = (const float*)d_in[7];
    const float* W2    = (const float*)d_in[8];
    const float* as2   = (const float*)d_in[9];
    const float* ad2   = (const float*)d_in[10];
    const float* b2    = (const float*)d_in[11];
    const float* dw1   = (const float*)d_in[12];
    const float* db1   = (const float*)d_in[13];
    const float* dw2   = (const float*)d_in[14];
    const float* db2   = (const float*)d_in[15];
    const float* dw3   = (const float*)d_in[16];
    const float* db3   = (const float*)d_in[17];
    float* out = (float*)d_out;

    int N = in_sizes[0] / IN_NODE;
    int M = in_sizes[1] / 2;
    if (N > NMAX || M > EMAX || N <= 0 || M <= 0) return;

    const int* srcp = ei;
    const int* dstp = ei + M;
    int nb = (N + 1023) / 1024;

    k_zero<<<(N + 255) / 256, 256>>>(N);
    k_prep<<<1, 256>>>(u, W1, dw2);
    k_hist<<<(M + 255) / 256, 256>>>(dstp, M);
    k_scan1<<<nb, 1024>>>(N);
    k_scan3<<<(N + 255) / 256, 256>>>(nb, N, M);
    k_scatter<<<(M + 255) / 256, 256>>>(srcp, dstp, M);

    k_gemm1<<<(N + 3) / 4, 128>>>(x, as1, ad1, N);
    k_agg<<<(N + 3) / 4, 128>>>(b1, 1, N);

    k_gemm2<<<(N + G2N - 1) / G2N, 128>>>(W2, as2, ad2, N);
    k_agg<<<(N + 3) / 4, 128>>>(b2, 0, N);

    k_pab<<<(N + 15) / 16, 256>>>(dw1, N);
    k_dec<<<1184, 256>>>(ei, eattr, dw1, db1, db2, dw3, db3, out, M);
}

// round 9
// speedup vs baseline: 1.6805x; 1.6805x over previous
#include <cuda_runtime.h>
#include <math.h>

#define NMAX 100000
#define EMAX 1600000
#define HEADS 4
#define HID 32
#define F1 128
#define IN_NODE 12
#define IN_GLB 11
#define IN1 23
#define EDGE_DIM 5
#define DEC_IN 69
#define DEC_H1 64
#define DEC_H2 32
#define DEC_OUT 4

typedef unsigned long long ull;

__device__ float g_g[NMAX * F1];
__device__ float g_h1[NMAX * F1];
__device__ float g_h2[NMAX * HID];
__device__ float g_pa[NMAX * DEC_H1];
__device__ float g_pb[NMAX * DEC_H1];
__device__ __align__(16) float g_als[NMAX * HEADS];
__device__ __align__(16) float g_ald[NMAX * HEADS];
__device__ int   g_cnt[NMAX];
__device__ int   g_off[NMAX + 1];
__device__ int   g_cur[NMAX];
__device__ int   g_srcs[EMAX];
__device__ int   g_bsum[128];
__device__ float g_t1[F1];
__device__ float g_w1tt[IN_NODE * F1];
__device__ float g_w2t[DEC_H1 * DEC_H2];
__device__ __align__(16) ull g_w2p[F1 * F1];   // W2 transposed+splatted: [k][f] = (w,w)

__device__ __forceinline__ float lrelu02(float x) { return x > 0.f ? x : 0.2f * x; }
__device__ __forceinline__ float eluf(float x)    { return x > 0.f ? x : expm1f(x); }

// ---- packed f32x2 helpers ---------------------------------------------------
__device__ __forceinline__ ull pk2(float lo, float hi) {
    ull r;
    asm("mov.b64 %0, {%1, %2};" : "=l"(r) : "f"(lo), "f"(hi));
    return r;
}
__device__ __forceinline__ void fma2(ull& d, ull a, ull b) {
    asm("fma.rn.f32x2 %0, %1, %2, %0;" : "+l"(d) : "l"(a), "l"(b));
}
__device__ __forceinline__ float2 upk2(ull v) {
    float2 f;
    asm("mov.b64 {%0, %1}, %2;" : "=f"(f.x), "=f"(f.y) : "l"(v));
    return f;
}

// ---------------- prep ------------------------------------------------------
__global__ void k_prep(const float* __restrict__ u, const float* __restrict__ W1,
                       const float* __restrict__ dw2) {
    int tid = threadIdx.x;
    if (tid < F1) {
        float s = 0.f;
        #pragma unroll
        for (int k = 0; k < IN_GLB; k++) s += u[k] * W1[tid * IN1 + IN_NODE + k];
        g_t1[tid] = s;
    }
    for (int i = tid; i < IN_NODE * F1; i += blockDim.x) {
        int k = i >> 7, f = i & 127;
        g_w1tt[i] = W1[f * IN1 + k];
    }
    for (int i = tid; i < DEC_H1 * DEC_H2; i += blockDim.x) {
        int k = i >> 5, o = i & 31;
        g_w2t[i] = dw2[o * DEC_H1 + k];
    }
}

// W2 -> [k][f] splatted u64 pairs
__global__ void k_prep2(const float* __restrict__ W2) {
    int i = blockIdx.x * 256 + threadIdx.x;   // 16384 total
    int k = i >> 7, f = i & 127;
    float w = W2[f * F1 + k];
    g_w2p[i] = pk2(w, w);
}

// ---------------- layer-1 node transform + attention logits ----------------
__global__ void k_gemm1(const float* __restrict__ x,
                        const float* __restrict__ asrc, const float* __restrict__ adst,
                        int N) {
    int n0 = blockIdx.x * 4;
    int f = threadIdx.x;
    __shared__ float xs[4][IN_NODE];
    if (f < 4 * IN_NODE) {
        int i = f / IN_NODE, k = f - i * IN_NODE;
        int n = n0 + i;
        xs[i][k] = (n < N) ? x[n * IN_NODE + k] : 0.f;
    }
    __syncthreads();
    float acc[4];
    float t = g_t1[f];
    #pragma unroll
    for (int i = 0; i < 4; i++) acc[i] = t;
    #pragma unroll
    for (int k = 0; k < IN_NODE; k++) {
        float w = g_w1tt[k * F1 + f];
        #pragma unroll
        for (int i = 0; i < 4; i++) acc[i] += xs[i][k] * w;
    }
    int h = f >> 5;
    float cas = asrc[f], cad = adst[f];
    #pragma unroll
    for (int i = 0; i < 4; i++) {
        int n = n0 + i;
        if (n >= N) break;
        g_g[n * F1 + f] = acc[i];
        float vs = acc[i] * cas, vd = acc[i] * cad;
        #pragma unroll
        for (int o = 16; o; o >>= 1) {
            vs += __shfl_xor_sync(0xffffffffu, vs, o);
            vd += __shfl_xor_sync(0xffffffffu, vd, o);
        }
        if ((f & 31) == 0) {
            g_als[n * HEADS + h] = vs;
            g_ald[n * HEADS + h] = vd;
        }
    }
}

// ---------------- layer-2 node transform: 32 nodes/block, 4f x 8n tiles -----
// thread: fq = tid>>2 (f0 = 4*fq), nq = tid&3 (nn0 = 8*nq). warp w == head w.
#define G2N 32
#define HSTS 36   // padded stride (16B-aligned per k, low STS conflicts)
__global__ __launch_bounds__(128) void k_gemm2(const float* __restrict__ asrc,
                                               const float* __restrict__ adst,
                                               int N) {
    __shared__ __align__(16) float hst[F1 * HSTS];
    int tid = threadIdx.x;
    int n0 = blockIdx.x * G2N;

    // load h1 tile: [k=f][n], coalesced gmem reads, 2-way-conflict STS
    for (int i = tid; i < G2N * (F1 / 4); i += 128) {
        int n = i >> 5, f4 = i & 31;
        float4 hv = make_float4(0.f, 0.f, 0.f, 0.f);
        if (n0 + n < N)
            hv = *reinterpret_cast<const float4*>(&g_h1[(size_t)(n0 + n) * F1 + 4 * f4]);
        hst[(4 * f4 + 0) * HSTS + n] = hv.x;
        hst[(4 * f4 + 1) * HSTS + n] = hv.y;
        hst[(4 * f4 + 2) * HSTS + n] = hv.z;
        hst[(4 * f4 + 3) * HSTS + n] = hv.w;
    }
    __syncthreads();

    int fq = tid >> 2, nq = tid & 3;
    int f0 = fq * 4, nn0 = nq * 8;

    ull acc[4][4];   // [f][n-pair]
    #pragma unroll
    for (int a = 0; a < 4; a++)
        #pragma unroll
        for (int b = 0; b < 4; b++) acc[a][b] = 0ull;

    #pragma unroll 4
    for (int k = 0; k < F1; k++) {
        ulonglong2 h01 = *reinterpret_cast<const ulonglong2*>(&hst[k * HSTS + nn0]);
        ulonglong2 h23 = *reinterpret_cast<const ulonglong2*>(&hst[k * HSTS + nn0 + 4]);
        const ulonglong2* wp = reinterpret_cast<const ulonglong2*>(&g_w2p[(size_t)k * F1 + f0]);
        ulonglong2 w01 = wp[0];
        ulonglong2 w23 = wp[1];
        fma2(acc[0][0], h01.x, w01.x); fma2(acc[0][1], h01.y, w01.x);
        fma2(acc[0][2], h23.x, w01.x); fma2(acc[0][3], h23.y, w01.x);
        fma2(acc[1][0], h01.x, w01.y); fma2(acc[1][1], h01.y, w01.y);
        fma2(acc[1][2], h23.x, w01.y); fma2(acc[1][3], h23.y, w01.y);
        fma2(acc[2][0], h01.x, w23.x); fma2(acc[2][1], h01.y, w23.x);
        fma2(acc[2][2], h23.x, w23.x); fma2(acc[2][3], h23.y, w23.x);
        fma2(acc[3][0], h01.x, w23.y); fma2(acc[3][1], h01.y, w23.y);
        fma2(acc[3][2], h23.x, w23.y); fma2(acc[3][3], h23.y, w23.y);
    }

    // unpack: av[f][n]
    float av[4][8];
    #pragma unroll
    for (int f = 0; f < 4; f++)
        #pragma unroll
        for (int p = 0; p < 4; p++) {
            float2 t = upk2(acc[f][p]);
            av[f][2 * p] = t.x;
            av[f][2 * p + 1] = t.y;
        }

    float4 cas = *reinterpret_cast<const float4*>(&asrc[f0]);
    float4 cad = *reinterpret_cast<const float4*>(&adst[f0]);
    float vs[8], vd[8];
    #pragma unroll
    for (int j = 0; j < 8; j++) {
        int n = n0 + nn0 + j;
        if (n < N) {
            float4 o = make_float4(av[0][j], av[1][j], av[2][j], av[3][j]);
            *reinterpret_cast<float4*>(&g_g[(size_t)n * F1 + f0]) = o;
        }
        vs[j] = av[0][j] * cas.x + av[1][j] * cas.y + av[2][j] * cas.z + av[3][j] * cas.w;
        vd[j] = av[0][j] * cad.x + av[1][j] * cad.y + av[2][j] * cad.z + av[3][j] * cad.w;
    }
    #pragma unroll
    for (int j = 0; j < 8; j++) {
        #pragma unroll
        for (int m = 4; m <= 16; m <<= 1) {
            vs[j] += __shfl_xor_sync(0xffffffffu, vs[j], m);
            vd[j] += __shfl_xor_sync(0xffffffffu, vd[j], m);
        }
    }
    if ((tid & 28) == 0) {   // one lane per (warp, nq)
        int h = tid >> 5;
        #pragma unroll
        for (int j = 0; j < 8; j++) {
            int n = n0 + nn0 + j;
            if (n < N) {
                g_als[n * HEADS + h] = vs[j];
                g_ald[n * HEADS + h] = vd[j];
            }
        }
    }
}

// ---------------- CSR build --------------------------------------------------
__global__ void k_zero(int N) {
    int i = blockIdx.x * blockDim.x + threadIdx.x;
    if (i < N) g_cnt[i] = 0;
}
__global__ void k_hist(const int* __restrict__ dst, int M) {
    int e = blockIdx.x * blockDim.x + threadIdx.x;
    if (e < M) atomicAdd(&g_cnt[dst[e]], 1);
}
__global__ void k_scan1(int N) {
    __shared__ int sh[1024];
    int tid = threadIdx.x;
    int i = blockIdx.x * 1024 + tid;
    int v = (i < N) ? g_cnt[i] : 0;
    sh[tid] = v;
    __syncthreads();
    for (int o = 1; o < 1024; o <<= 1) {
        int t = (tid >= o) ? sh[tid - o] : 0;
        __syncthreads();
        sh[tid] += t;
        __syncthreads();
    }
    if (i < N) g_off[i] = sh[tid] - v;
    if (tid == 1023) g_bsum[blockIdx.x] = sh[1023];
}
__global__ void k_scan3(int nb, int N, int M) {
    __shared__ int sh[128];
    int tid = threadIdx.x;
    if (tid < 128) {
        int v = (tid < nb) ? g_bsum[tid] : 0;
        sh[tid] = v;
    }
    __syncthreads();
    if (tid < 128) {
        for (int o = 1; o < 128; o <<= 1) {
            int t = (tid >= o) ? sh[tid - o] : 0;
            __syncthreads();
            sh[tid] += t;
            __syncthreads();
        }
    } else {
        for (int o = 1; o < 128; o <<= 1) { __syncthreads(); __syncthreads(); }
    }
    int i = blockIdx.x * blockDim.x + tid;
    if (i < N) {
        int blk = i >> 10;
        int ex = (blk == 0) ? 0 : sh[blk - 1];
        int v = g_off[i] + ex;
        g_off[i] = v;
        g_cur[i] = v;
    }
    if (i == 0) g_off[N] = M;
}
__global__ void k_scatter(const int* __restrict__ src, const int* __restrict__ dst, int M) {
    int e = blockIdx.x * blockDim.x + threadIdx.x;
    if (e < M) {
        int d = dst[e];
        int p = atomicAdd(&g_cur[d], 1);
        g_srcs[p] = src[e];
    }
}

// ---------------- GAT aggregation (R6-exact: 4 warps/node, pipelined) -------
__global__ void k_agg(const float* __restrict__ bias, int concat, int N) {
    int n = blockIdx.x;
    if (n >= N) return;
    int h = threadIdx.x >> 5;
    int lane = threadIdx.x & 31;
    int beg = g_off[n], end = g_off[n + 1];

    float ad = g_ald[n * HEADS + h];
    float ws = __expf(lrelu02(g_als[n * HEADS + h] + ad));

    const float* gg = g_g + (h << 5) + lane;
    float acc = ws * gg[(size_t)n * F1];
    float psum = 0.f;
    for (int base = beg; base < end; base += 32) {
        int j = base + lane;
        float w = 0.f;
        int s = 0;
        if (j < end) {
            s = g_srcs[j];
            w = __expf(lrelu02(g_als[s * HEADS + h] + ad));
            psum += w;
        }
        int lim = min(32, end - base);
        int kk = 0;
        for (; kk + 4 <= lim; kk += 4) {
            float w0 = __shfl_sync(0xffffffffu, w, kk);
            float w1 = __shfl_sync(0xffffffffu, w, kk + 1);
            float w2 = __shfl_sync(0xffffffffu, w, kk + 2);
            float w3 = __shfl_sync(0xffffffffu, w, kk + 3);
            int s0 = __shfl_sync(0xffffffffu, s, kk);
            int s1 = __shfl_sync(0xffffffffu, s, kk + 1);
            int s2 = __shfl_sync(0xffffffffu, s, kk + 2);
            int s3 = __shfl_sync(0xffffffffu, s, kk + 3);
            float v0 = gg[(size_t)s0 * F1];
            float v1 = gg[(size_t)s1 * F1];
            float v2 = gg[(size_t)s2 * F1];
            float v3 = gg[(size_t)s3 * F1];
            acc += w0 * v0;
            acc += w1 * v1;
            acc += w2 * v2;
            acc += w3 * v3;
        }
        for (; kk < lim; kk++) {
            float wk = __shfl_sync(0xffffffffu, w, kk);
            int sk = __shfl_sync(0xffffffffu, s, kk);
            acc += wk * gg[(size_t)sk * F1];
        }
    }
    #pragma unroll
    for (int o = 16; o; o >>= 1) psum += __shfl_xor_sync(0xffffffffu, psum, o);
    float v = acc / (psum + ws);

    if (concat) {
        v += bias[(h << 5) + lane];
        g_h1[n * F1 + (h << 5) + lane] = eluf(v);
    } else {
        __shared__ float sm[F1];
        sm[(h << 5) + lane] = v;
        __syncthreads();
        if (h == 0) {
            float t = (sm[lane] + sm[32 + lane] + sm[64 + lane] + sm[96 + lane]) * 0.25f
                      + bias[lane];
            g_h2[n * HID + lane] = eluf(t);
        }
    }
}

// ---------------- decoder precompute: pa/pb (tiled, smem weights) -----------
__global__ __launch_bounds__(256) void k_pab(const float* __restrict__ dw1, int N) {
    __shared__ float sdw[64 * 65];
    __shared__ float sh2[16 * 32];
    int tid = threadIdx.x;
    for (int i = tid; i < 64 * 64; i += 256) {
        int o = i >> 6, k = i & 63;
        sdw[o * 65 + k] = dw1[o * DEC_IN + k];
    }
    int n0 = blockIdx.x * 16;
    for (int i = tid; i < 16 * 32; i += 256) {
        int nl = i >> 5, k = i & 31;
        int n = n0 + nl;
        sh2[i] = (n < N) ? g_h2[n * HID + k] : 0.f;
    }
    __syncthreads();
    int o = tid & 63, ng = tid >> 6;
    float pa[4] = {0.f, 0.f, 0.f, 0.f}, pb[4] = {0.f, 0.f, 0.f, 0.f};
    #pragma unroll
    for (int k = 0; k < 32; k++) {
        float wa = sdw[o * 65 + k];
        float wb = sdw[o * 65 + 32 + k];
        #pragma unroll
        for (int j = 0; j < 4; j++) {
            float hv = sh2[(ng * 4 + j) * 32 + k];
            pa[j] += wa * hv;
            pb[j] += wb * hv;
        }
    }
    #pragma unroll
    for (int j = 0; j < 4; j++) {
        int n = n0 + ng * 4 + j;
        if (n < N) {
            g_pa[n * 64 + o] = pa[j];
            g_pb[n * 64 + o] = pb[j];
        }
    }
}

// ---------------- decoder: 64-edge tiles; GEMM2 4e x 4o on 4 warps ----------
#define TB 64
#define ZS (TB + 4)
__global__ __launch_bounds__(256) void k_dec(
    const int* __restrict__ ei, const float* __restrict__ eattr,
    const float* __restrict__ dw1, const float* __restrict__ db1,
    const float* __restrict__ db2, const float* __restrict__ dw3,
    const float* __restrict__ db3, float* __restrict__ out, int M) {
    __shared__ __align__(16) ull sw2p[DEC_H1 * DEC_H2];
    __shared__ float sw3[DEC_H2 * DEC_OUT];
    __shared__ float sb2[DEC_H2];
    __shared__ float sb3[DEC_OUT];
    __shared__ float sw1c[EDGE_DIM * 64];
    __shared__ float sdb1[64];
    __shared__ int ssrc[TB], sdst[TB];
    __shared__ float eat[TB * EDGE_DIM];
    __shared__ __align__(16) float z1t[DEC_H1 * ZS];
    __shared__ __align__(16) float z2t[DEC_H2 * ZS];
    int tid = threadIdx.x;

    for (int i = tid; i < DEC_H1 * DEC_H2; i += 256) {
        float w = g_w2t[i];
        sw2p[i] = pk2(w, w);
    }
    if (tid < 128) sw3[tid] = dw3[tid];
    if (tid < 64)  sdb1[tid] = db1[tid];
    if (tid < 32)  sb2[tid] = db2[tid];
    if (tid < 4)   sb3[tid] = db3[tid];
    for (int i = tid; i < EDGE_DIM * 64; i += 256) {
        int k = i >> 6, o = i & 63;
        sw1c[i] = dw1[o * DEC_IN + 64 + k];
    }

    const int* srcp = ei;
    const int* dstp = ei + M;
    int ntiles = (M + TB - 1) / TB;
    // GEMM2 mapping (tid < 128): eg = tid&15 (e0=4eg), og = tid>>4 (o0=4og)
    int eg = tid & 15, og = tid >> 4;
    int e0 = eg * 4, o0 = og * 4;

    for (int tile = blockIdx.x; tile < ntiles; tile += gridDim.x) {
        int eb = tile * TB;
        int nE = min(TB, M - eb);
        __syncthreads();
        if (tid < TB) {
            ssrc[tid] = (tid < nE) ? srcp[eb + tid] : 0;
            sdst[tid] = (tid < nE) ? dstp[eb + tid] : 0;
        }
        for (int i = tid; i < TB * EDGE_DIM; i += 256) {
            int gi = eb * EDGE_DIM + i;
            eat[i] = (gi < M * EDGE_DIM) ? eattr[gi] : 0.f;
        }
        __syncthreads();

        for (int i = tid; i < TB * 64; i += 256) {
            int e = i >> 6, o = i & 63;
            float v = g_pa[(size_t)ssrc[e] * 64 + o] + g_pb[(size_t)sdst[e] * 64 + o]
                      + sdb1[o];
            #pragma unroll
            for (int k = 0; k < EDGE_DIM; k++) v += sw1c[k * 64 + o] * eat[e * EDGE_DIM + k];
            z1t[o * ZS + e] = fmaxf(v, 0.f);
        }
        __syncthreads();

        if (tid < 128) {
            ull acc[4][2];   // [o][e-pair]
            #pragma unroll
            for (int a = 0; a < 4; a++) { acc[a][0] = 0ull; acc[a][1] = 0ull; }
            #pragma unroll 8
            for (int k = 0; k < DEC_H1; k++) {
                ulonglong2 zp = *reinterpret_cast<const ulonglong2*>(&z1t[k * ZS + e0]);
                ulonglong2 w01 = *reinterpret_cast<const ulonglong2*>(&sw2p[k * DEC_H2 + o0]);
                ulonglong2 w23 = *reinterpret_cast<const ulonglong2*>(&sw2p[k * DEC_H2 + o0 + 2]);
                fma2(acc[0][0], zp.x, w01.x); fma2(acc[0][1], zp.y, w01.x);
                fma2(acc[1][0], zp.x, w01.y); fma2(acc[1][1], zp.y, w01.y);
                fma2(acc[2][0], zp.x, w23.x); fma2(acc[2][1], zp.y, w23.x);
                fma2(acc[3][0], zp.x, w23.y); fma2(acc[3][1], zp.y, w23.y);
            }
            #pragma unroll
            for (int o = 0; o < 4; o++) {
                float b = sb2[o0 + o];
                float2 t0 = upk2(acc[o][0]);
                float2 t1 = upk2(acc[o][1]);
                float4 ov = make_float4(fmaxf(t0.x + b, 0.f), fmaxf(t0.y + b, 0.f),
                                        fmaxf(t1.x + b, 0.f), fmaxf(t1.y + b, 0.f));
                *reinterpret_cast<float4*>(&z2t[(o0 + o) * ZS + e0]) = ov;
            }
        }
        __syncthreads();

        {
            int e = tid & 63, o = tid >> 6;
            float acc = sb3[o];
            #pragma unroll
            for (int k = 0; k < DEC_H2; k++) acc += z2t[k * ZS + e] * sw3[o * DEC_H2 + k];
            if (e < nE) out[(eb + e) * DEC_OUT + o] = acc;
        }
    }
}

// ---------------- launch -----------------------------------------------------
extern "C" void kernel_launch(void* const* d_in, const int* in_sizes, int n_in,
                              void* d_out, int out_size) {
    const float* x     = (const float*)d_in[0];
    const int*   ei    = (const int*)d_in[1];
    const float* eattr = (const float*)d_in[2];
    const float* u     = (const float*)d_in[3];
    const float* W1    = (const float*)d_in[4];
    const float* as1   = (const float*)d_in[5];
    const float* ad1   = (const float*)d_in[6];
    const float* b1    = (const float*)d_in[7];
    const float* W2    = (const float*)d_in[8];
    const float* as2   = (const float*)d_in[9];
    const float* ad2   = (const float*)d_in[10];
    const float* b2    = (const float*)d_in[11];
    const float* dw1   = (const float*)d_in[12];
    const float* db1   = (const float*)d_in[13];
    const float* dw2   = (const float*)d_in[14];
    const float* db2   = (const float*)d_in[15];
    const float* dw3   = (const float*)d_in[16];
    const float* db3   = (const float*)d_in[17];
    float* out = (float*)d_out;

    int N = in_sizes[0] / IN_NODE;
    int M = in_sizes[1] / 2;
    if (N > NMAX || M > EMAX || N <= 0 || M <= 0) return;

    const int* srcp = ei;
    const int* dstp = ei + M;
    int nb = (N + 1023) / 1024;

    k_zero<<<(N + 255) / 256, 256>>>(N);
    k_prep<<<1, 256>>>(u, W1, dw2);
    k_prep2<<<64, 256>>>(W2);
    k_hist<<<(M + 255) / 256, 256>>>(dstp, M);
    k_scan1<<<nb, 1024>>>(N);
    k_scan3<<<(N + 255) / 256, 256>>>(nb, N, M);
    k_scatter<<<(M + 255) / 256, 256>>>(srcp, dstp, M);

    k_gemm1<<<(N + 3) / 4, 128>>>(x, as1, ad1, N);
    k_agg<<<N, 128>>>(b1, 1, N);

    k_gemm2<<<(N + G2N - 1) / G2N, 128>>>(as2, ad2, N);
    k_agg<<<N, 128>>>(b2, 0, N);

    k_pab<<<(N + 15) / 16, 256>>>(dw1, N);
    k_dec<<<1184, 256>>>(ei, eattr, dw1, db1, db2, dw3, db3, out, M);
}

// round 10
// speedup vs baseline: 1.7198x; 1.0234x over previous
#include <cuda_runtime.h>
#include <math.h>

#define NMAX 100000
#define EMAX 1600000
#define HEADS 4
#define HID 32
#define F1 128
#define IN_NODE 12
#define IN_GLB 11
#define IN1 23
#define EDGE_DIM 5
#define DEC_IN 69
#define DEC_H1 64
#define DEC_H2 32
#define DEC_OUT 4

typedef unsigned long long ull;

__device__ float g_g[NMAX * F1];
__device__ float g_h1[NMAX * F1];
__device__ float g_h2[NMAX * HID];
__device__ float g_pa[NMAX * DEC_H1];
__device__ float g_pb[NMAX * DEC_H1];
__device__ __align__(16) float g_als[NMAX * HEADS];
__device__ __align__(16) float g_ald[NMAX * HEADS];
__device__ int   g_cnt[NMAX];
__device__ int   g_off[NMAX + 1];
__device__ int   g_cur[NMAX];
__device__ int   g_srcs[EMAX];
__device__ int   g_bsum[128];
__device__ float g_t1[F1];
__device__ float g_w1tt[IN_NODE * F1];
__device__ float g_w2t[DEC_H1 * DEC_H2];
__device__ __align__(16) ull g_w2p[F1 * F1];   // W2 transposed+splatted: [k][f] = (w,w)

__device__ __forceinline__ float lrelu02(float x) { return x > 0.f ? x : 0.2f * x; }
__device__ __forceinline__ float eluf(float x)    { return x > 0.f ? x : expm1f(x); }

// ---- packed f32x2 helpers ---------------------------------------------------
__device__ __forceinline__ ull pk2(float lo, float hi) {
    ull r;
    asm("mov.b64 %0, {%1, %2};" : "=l"(r) : "f"(lo), "f"(hi));
    return r;
}
__device__ __forceinline__ void fma2(ull& d, ull a, ull b) {
    asm("fma.rn.f32x2 %0, %1, %2, %0;" : "+l"(d) : "l"(a), "l"(b));
}
__device__ __forceinline__ float2 upk2(ull v) {
    float2 f;
    asm("mov.b64 {%0, %1}, %2;" : "=f"(f.x), "=f"(f.y) : "l"(v));
    return f;
}

// ---------------- prep ------------------------------------------------------
__global__ void k_prep(const float* __restrict__ u, const float* __restrict__ W1,
                       const float* __restrict__ dw2) {
    int tid = threadIdx.x;
    if (tid < F1) {
        float s = 0.f;
        #pragma unroll
        for (int k = 0; k < IN_GLB; k++) s += u[k] * W1[tid * IN1 + IN_NODE + k];
        g_t1[tid] = s;
    }
    for (int i = tid; i < IN_NODE * F1; i += blockDim.x) {
        int k = i >> 7, f = i & 127;
        g_w1tt[i] = W1[f * IN1 + k];
    }
    for (int i = tid; i < DEC_H1 * DEC_H2; i += blockDim.x) {
        int k = i >> 5, o = i & 31;
        g_w2t[i] = dw2[o * DEC_H1 + k];
    }
}

// W2 -> [k][f] splatted u64 pairs
__global__ void k_prep2(const float* __restrict__ W2) {
    int i = blockIdx.x * 256 + threadIdx.x;   // 16384 total
    int k = i >> 7, f = i & 127;
    float w = W2[f * F1 + k];
    g_w2p[i] = pk2(w, w);
}

// ---------------- layer-1 node transform + attention logits ----------------
__global__ void k_gemm1(const float* __restrict__ x,
                        const float* __restrict__ asrc, const float* __restrict__ adst,
                        int N) {
    int n0 = blockIdx.x * 4;
    int f = threadIdx.x;
    __shared__ float xs[4][IN_NODE];
    if (f < 4 * IN_NODE) {
        int i = f / IN_NODE, k = f - i * IN_NODE;
        int n = n0 + i;
        xs[i][k] = (n < N) ? __ldcs(&x[n * IN_NODE + k]) : 0.f;
    }
    __syncthreads();
    float acc[4];
    float t = g_t1[f];
    #pragma unroll
    for (int i = 0; i < 4; i++) acc[i] = t;
    #pragma unroll
    for (int k = 0; k < IN_NODE; k++) {
        float w = g_w1tt[k * F1 + f];
        #pragma unroll
        for (int i = 0; i < 4; i++) acc[i] += xs[i][k] * w;
    }
    int h = f >> 5;
    float cas = asrc[f], cad = adst[f];
    #pragma unroll
    for (int i = 0; i < 4; i++) {
        int n = n0 + i;
        if (n >= N) break;
        g_g[n * F1 + f] = acc[i];
        float vs = acc[i] * cas, vd = acc[i] * cad;
        #pragma unroll
        for (int o = 16; o; o >>= 1) {
            vs += __shfl_xor_sync(0xffffffffu, vs, o);
            vd += __shfl_xor_sync(0xffffffffu, vd, o);
        }
        if ((f & 31) == 0) {
            g_als[n * HEADS + h] = vs;
            g_ald[n * HEADS + h] = vd;
        }
    }
}

// ---------------- layer-2 node transform: 32 nodes/block, 4f x 8n tiles -----
#define G2N 32
#define HSTS 36
__global__ __launch_bounds__(128) void k_gemm2(const float* __restrict__ asrc,
                                               const float* __restrict__ adst,
                                               int N) {
    __shared__ __align__(16) float hst[F1 * HSTS];
    int tid = threadIdx.x;
    int n0 = blockIdx.x * G2N;

    // load h1 tile (streaming: h1 is read exactly once chip-wide)
    for (int i = tid; i < G2N * (F1 / 4); i += 128) {
        int n = i >> 5, f4 = i & 31;
        float4 hv = make_float4(0.f, 0.f, 0.f, 0.f);
        if (n0 + n < N)
            hv = __ldcs(reinterpret_cast<const float4*>(&g_h1[(size_t)(n0 + n) * F1 + 4 * f4]));
        hst[(4 * f4 + 0) * HSTS + n] = hv.x;
        hst[(4 * f4 + 1) * HSTS + n] = hv.y;
        hst[(4 * f4 + 2) * HSTS + n] = hv.z;
        hst[(4 * f4 + 3) * HSTS + n] = hv.w;
    }
    __syncthreads();

    int fq = tid >> 2, nq = tid & 3;
    int f0 = fq * 4, nn0 = nq * 8;

    ull acc[4][4];
    #pragma unroll
    for (int a = 0; a < 4; a++)
        #pragma unroll
        for (int b = 0; b < 4; b++) acc[a][b] = 0ull;

    #pragma unroll 4
    for (int k = 0; k < F1; k++) {
        ulonglong2 h01 = *reinterpret_cast<const ulonglong2*>(&hst[k * HSTS + nn0]);
        ulonglong2 h23 = *reinterpret_cast<const ulonglong2*>(&hst[k * HSTS + nn0 + 4]);
        const ulonglong2* wp = reinterpret_cast<const ulonglong2*>(&g_w2p[(size_t)k * F1 + f0]);
        ulonglong2 w01 = wp[0];
        ulonglong2 w23 = wp[1];
        fma2(acc[0][0], h01.x, w01.x); fma2(acc[0][1], h01.y, w01.x);
        fma2(acc[0][2], h23.x, w01.x); fma2(acc[0][3], h23.y, w01.x);
        fma2(acc[1][0], h01.x, w01.y); fma2(acc[1][1], h01.y, w01.y);
        fma2(acc[1][2], h23.x, w01.y); fma2(acc[1][3], h23.y, w01.y);
        fma2(acc[2][0], h01.x, w23.x); fma2(acc[2][1], h01.y, w23.x);
        fma2(acc[2][2], h23.x, w23.x); fma2(acc[2][3], h23.y, w23.x);
        fma2(acc[3][0], h01.x, w23.y); fma2(acc[3][1], h01.y, w23.y);
        fma2(acc[3][2], h23.x, w23.y); fma2(acc[3][3], h23.y, w23.y);
    }

    float av[4][8];
    #pragma unroll
    for (int f = 0; f < 4; f++)
        #pragma unroll
        for (int p = 0; p < 4; p++) {
            float2 t = upk2(acc[f][p]);
            av[f][2 * p] = t.x;
            av[f][2 * p + 1] = t.y;
        }

    float4 cas = *reinterpret_cast<const float4*>(&asrc[f0]);
    float4 cad = *reinterpret_cast<const float4*>(&adst[f0]);
    float vs[8], vd[8];
    #pragma unroll
    for (int j = 0; j < 8; j++) {
        int n = n0 + nn0 + j;
        if (n < N) {
            float4 o = make_float4(av[0][j], av[1][j], av[2][j], av[3][j]);
            *reinterpret_cast<float4*>(&g_g[(size_t)n * F1 + f0]) = o;
        }
        vs[j] = av[0][j] * cas.x + av[1][j] * cas.y + av[2][j] * cas.z + av[3][j] * cas.w;
        vd[j] = av[0][j] * cad.x + av[1][j] * cad.y + av[2][j] * cad.z + av[3][j] * cad.w;
    }
    #pragma unroll
    for (int j = 0; j < 8; j++) {
        #pragma unroll
        for (int m = 4; m <= 16; m <<= 1) {
            vs[j] += __shfl_xor_sync(0xffffffffu, vs[j], m);
            vd[j] += __shfl_xor_sync(0xffffffffu, vd[j], m);
        }
    }
    if ((tid & 28) == 0) {
        int h = tid >> 5;
        #pragma unroll
        for (int j = 0; j < 8; j++) {
            int n = n0 + nn0 + j;
            if (n < N) {
                g_als[n * HEADS + h] = vs[j];
                g_ald[n * HEADS + h] = vd[j];
            }
        }
    }
}

// ---------------- CSR build --------------------------------------------------
__global__ void k_zero(int N) {
    int i = blockIdx.x * blockDim.x + threadIdx.x;
    if (i < N) g_cnt[i] = 0;
}
__global__ void k_hist(const int* __restrict__ dst, int M) {
    int e = blockIdx.x * blockDim.x + threadIdx.x;
    if (e < M) atomicAdd(&g_cnt[__ldcs(&dst[e])], 1);
}
__global__ void k_scan1(int N) {
    __shared__ int sh[1024];
    int tid = threadIdx.x;
    int i = blockIdx.x * 1024 + tid;
    int v = (i < N) ? g_cnt[i] : 0;
    sh[tid] = v;
    __syncthreads();
    for (int o = 1; o < 1024; o <<= 1) {
        int t = (tid >= o) ? sh[tid - o] : 0;
        __syncthreads();
        sh[tid] += t;
        __syncthreads();
    }
    if (i < N) g_off[i] = sh[tid] - v;
    if (tid == 1023) g_bsum[blockIdx.x] = sh[1023];
}
__global__ void k_scan3(int nb, int N, int M) {
    __shared__ int sh[128];
    int tid = threadIdx.x;
    if (tid < 128) {
        int v = (tid < nb) ? g_bsum[tid] : 0;
        sh[tid] = v;
    }
    __syncthreads();
    if (tid < 128) {
        for (int o = 1; o < 128; o <<= 1) {
            int t = (tid >= o) ? sh[tid - o] : 0;
            __syncthreads();
            sh[tid] += t;
            __syncthreads();
        }
    } else {
        for (int o = 1; o < 128; o <<= 1) { __syncthreads(); __syncthreads(); }
    }
    int i = blockIdx.x * blockDim.x + tid;
    if (i < N) {
        int blk = i >> 10;
        int ex = (blk == 0) ? 0 : sh[blk - 1];
        int v = g_off[i] + ex;
        g_off[i] = v;
        g_cur[i] = v;
    }
    if (i == 0) g_off[N] = M;
}
__global__ void k_scatter(const int* __restrict__ src, const int* __restrict__ dst, int M) {
    int e = blockIdx.x * blockDim.x + threadIdx.x;
    if (e < M) {
        int d = __ldcs(&dst[e]);
        int p = atomicAdd(&g_cur[d], 1);
        g_srcs[p] = __ldcs(&src[e]);
    }
}

// ---------------- GAT aggregation (R6: 4 warps/node, 4-wide pipeline) -------
__global__ void k_agg(const float* __restrict__ bias, int concat, int N) {
    int n = blockIdx.x;
    if (n >= N) return;
    int h = threadIdx.x >> 5;
    int lane = threadIdx.x & 31;
    int beg = g_off[n], end = g_off[n + 1];

    float ad = g_ald[n * HEADS + h];
    float ws = __expf(lrelu02(g_als[n * HEADS + h] + ad));

    const float* gg = g_g + (h << 5) + lane;
    float acc = ws * gg[(size_t)n * F1];
    float psum = 0.f;
    for (int base = beg; base < end; base += 32) {
        int j = base + lane;
        float w = 0.f;
        int s = 0;
        if (j < end) {
            s = g_srcs[j];
            w = __expf(lrelu02(g_als[s * HEADS + h] + ad));
            psum += w;
        }
        int lim = min(32, end - base);
        int kk = 0;
        for (; kk + 4 <= lim; kk += 4) {
            float w0 = __shfl_sync(0xffffffffu, w, kk);
            float w1 = __shfl_sync(0xffffffffu, w, kk + 1);
            float w2 = __shfl_sync(0xffffffffu, w, kk + 2);
            float w3 = __shfl_sync(0xffffffffu, w, kk + 3);
            int s0 = __shfl_sync(0xffffffffu, s, kk);
            int s1 = __shfl_sync(0xffffffffu, s, kk + 1);
            int s2 = __shfl_sync(0xffffffffu, s, kk + 2);
            int s3 = __shfl_sync(0xffffffffu, s, kk + 3);
            float v0 = gg[(size_t)s0 * F1];
            float v1 = gg[(size_t)s1 * F1];
            float v2 = gg[(size_t)s2 * F1];
            float v3 = gg[(size_t)s3 * F1];
            acc += w0 * v0;
            acc += w1 * v1;
            acc += w2 * v2;
            acc += w3 * v3;
        }
        for (; kk < lim; kk++) {
            float wk = __shfl_sync(0xffffffffu, w, kk);
            int sk = __shfl_sync(0xffffffffu, s, kk);
            acc += wk * gg[(size_t)sk * F1];
        }
    }
    #pragma unroll
    for (int o = 16; o; o >>= 1) psum += __shfl_xor_sync(0xffffffffu, psum, o);
    float v = acc / (psum + ws);

    if (concat) {
        v += bias[(h << 5) + lane];
        __stcs(&g_h1[n * F1 + (h << 5) + lane], eluf(v));   // streaming: read once later
    } else {
        __shared__ float sm[F1];
        sm[(h << 5) + lane] = v;
        __syncthreads();
        if (h == 0) {
            float t = (sm[lane] + sm[32 + lane] + sm[64 + lane] + sm[96 + lane]) * 0.25f
                      + bias[lane];
            g_h2[n * HID + lane] = eluf(t);
        }
    }
}

// ---------------- decoder precompute: pa/pb (tiled, smem weights) -----------
__global__ __launch_bounds__(256) void k_pab(const float* __restrict__ dw1, int N) {
    __shared__ float sdw[64 * 65];
    __shared__ float sh2[16 * 32];
    int tid = threadIdx.x;
    for (int i = tid; i < 64 * 64; i += 256) {
        int o = i >> 6, k = i & 63;
        sdw[o * 65 + k] = dw1[o * DEC_IN + k];
    }
    int n0 = blockIdx.x * 16;
    for (int i = tid; i < 16 * 32; i += 256) {
        int nl = i >> 5, k = i & 31;
        int n = n0 + nl;
        sh2[i] = (n < N) ? g_h2[n * HID + k] : 0.f;
    }
    __syncthreads();
    int o = tid & 63, ng = tid >> 6;
    float pa[4] = {0.f, 0.f, 0.f, 0.f}, pb[4] = {0.f, 0.f, 0.f, 0.f};
    #pragma unroll
    for (int k = 0; k < 32; k++) {
        float wa = sdw[o * 65 + k];
        float wb = sdw[o * 65 + 32 + k];
        #pragma unroll
        for (int j = 0; j < 4; j++) {
            float hv = sh2[(ng * 4 + j) * 32 + k];
            pa[j] += wa * hv;
            pb[j] += wb * hv;
        }
    }
    #pragma unroll
    for (int j = 0; j < 4; j++) {
        int n = n0 + ng * 4 + j;
        if (n < N) {
            g_pa[n * 64 + o] = pa[j];
            g_pb[n * 64 + o] = pb[j];
        }
    }
}

// ---------------- decoder: 64-edge tiles; GEMM2 4e x 4o on 4 warps ----------
#define TB 64
#define ZS (TB + 4)
__global__ __launch_bounds__(256) void k_dec(
    const int* __restrict__ ei, const float* __restrict__ eattr,
    const float* __restrict__ dw1, const float* __restrict__ db1,
    const float* __restrict__ db2, const float* __restrict__ dw3,
    const float* __restrict__ db3, float* __restrict__ out, int M) {
    __shared__ __align__(16) ull sw2p[DEC_H1 * DEC_H2];
    __shared__ float sw3[DEC_H2 * DEC_OUT];
    __shared__ float sb2[DEC_H2];
    __shared__ float sb3[DEC_OUT];
    __shared__ float sw1c[EDGE_DIM * 64];
    __shared__ float sdb1[64];
    __shared__ int ssrc[TB], sdst[TB];
    __shared__ float eat[TB * EDGE_DIM];
    __shared__ __align__(16) float z1t[DEC_H1 * ZS];
    __shared__ __align__(16) float z2t[DEC_H2 * ZS];
    int tid = threadIdx.x;

    for (int i = tid; i < DEC_H1 * DEC_H2; i += 256) {
        float w = g_w2t[i];
        sw2p[i] = pk2(w, w);
    }
    if (tid < 128) sw3[tid] = dw3[tid];
    if (tid < 64)  sdb1[tid] = db1[tid];
    if (tid < 32)  sb2[tid] = db2[tid];
    if (tid < 4)   sb3[tid] = db3[tid];
    for (int i = tid; i < EDGE_DIM * 64; i += 256) {
        int k = i >> 6, o = i & 63;
        sw1c[i] = dw1[o * DEC_IN + 64 + k];
    }

    const int* srcp = ei;
    const int* dstp = ei + M;
    int ntiles = (M + TB - 1) / TB;
    int eg = tid & 15, og = tid >> 4;
    int e0 = eg * 4, o0 = og * 4;

    for (int tile = blockIdx.x; tile < ntiles; tile += gridDim.x) {
        int eb = tile * TB;
        int nE = min(TB, M - eb);
        __syncthreads();
        if (tid < TB) {
            ssrc[tid] = (tid < nE) ? __ldcs(&srcp[eb + tid]) : 0;
            sdst[tid] = (tid < nE) ? __ldcs(&dstp[eb + tid]) : 0;
        }
        for (int i = tid; i < TB * EDGE_DIM; i += 256) {
            int gi = eb * EDGE_DIM + i;
            eat[i] = (gi < M * EDGE_DIM) ? __ldcs(&eattr[gi]) : 0.f;
        }
        __syncthreads();

        for (int i = tid; i < TB * 64; i += 256) {
            int e = i >> 6, o = i & 63;
            float v = g_pa[(size_t)ssrc[e] * 64 + o] + g_pb[(size_t)sdst[e] * 64 + o]
                      + sdb1[o];
            #pragma unroll
            for (int k = 0; k < EDGE_DIM; k++) v += sw1c[k * 64 + o] * eat[e * EDGE_DIM + k];
            z1t[o * ZS + e] = fmaxf(v, 0.f);
        }
        __syncthreads();

        if (tid < 128) {
            ull acc[4][2];
            #pragma unroll
            for (int a = 0; a < 4; a++) { acc[a][0] = 0ull; acc[a][1] = 0ull; }
            #pragma unroll 8
            for (int k = 0; k < DEC_H1; k++) {
                ulonglong2 zp = *reinterpret_cast<const ulonglong2*>(&z1t[k * ZS + e0]);
                ulonglong2 w01 = *reinterpret_cast<const ulonglong2*>(&sw2p[k * DEC_H2 + o0]);
                ulonglong2 w23 = *reinterpret_cast<const ulonglong2*>(&sw2p[k * DEC_H2 + o0 + 2]);
                fma2(acc[0][0], zp.x, w01.x); fma2(acc[0][1], zp.y, w01.x);
                fma2(acc[1][0], zp.x, w01.y); fma2(acc[1][1], zp.y, w01.y);
                fma2(acc[2][0], zp.x, w23.x); fma2(acc[2][1], zp.y, w23.x);
                fma2(acc[3][0], zp.x, w23.y); fma2(acc[3][1], zp.y, w23.y);
            }
            #pragma unroll
            for (int o = 0; o < 4; o++) {
                float b = sb2[o0 + o];
                float2 t0 = upk2(acc[o][0]);
                float2 t1 = upk2(acc[o][1]);
                float4 ov = make_float4(fmaxf(t0.x + b, 0.f), fmaxf(t0.y + b, 0.f),
                                        fmaxf(t1.x + b, 0.f), fmaxf(t1.y + b, 0.f));
                *reinterpret_cast<float4*>(&z2t[(o0 + o) * ZS + e0]) = ov;
            }
        }
        __syncthreads();

        {
            int e = tid & 63, o = tid >> 6;
            float acc = sb3[o];
            #pragma unroll
            for (int k = 0; k < DEC_H2; k++) acc += z2t[k * ZS + e] * sw3[o * DEC_H2 + k];
            if (e < nE) __stcs(&out[(eb + e) * DEC_OUT + o], acc);   // streaming out
        }
    }
}

// ---------------- launch -----------------------------------------------------
extern "C" void kernel_launch(void* const* d_in, const int* in_sizes, int n_in,
                              void* d_out, int out_size) {
    const float* x     = (const float*)d_in[0];
    const int*   ei    = (const int*)d_in[1];
    const float* eattr = (const float*)d_in[2];
    const float* u     = (const float*)d_in[3];
    const float* W1    = (const float*)d_in[4];
    const float* as1   = (const float*)d_in[5];
    const float* ad1   = (const float*)d_in[6];
    const float* b1    = (const float*)d_in[7];
    const float* W2    = (const float*)d_in[8];
    const float* as2   = (const float*)d_in[9];
    const float* ad2   = (const float*)d_in[10];
    const float* b2    = (const float*)d_in[11];
    const float* dw1   = (const float*)d_in[12];
    const float* db1   = (const float*)d_in[13];
    const float* dw2   = (const float*)d_in[14];
    const float* db2   = (const float*)d_in[15];
    const float* dw3   = (const float*)d_in[16];
    const float* db3   = (const float*)d_in[17];
    float* out = (float*)d_out;

    int N = in_sizes[0] / IN_NODE;
    int M = in_sizes[1] / 2;
    if (N > NMAX || M > EMAX || N <= 0 || M <= 0) return;

    const int* srcp = ei;
    const int* dstp = ei + M;
    int nb = (N + 1023) / 1024;

    k_zero<<<(N + 255) / 256, 256>>>(N);
    k_prep<<<1, 256>>>(u, W1, dw2);
    k_prep2<<<64, 256>>>(W2);
    k_hist<<<(M + 255) / 256, 256>>>(dstp, M);
    k_scan1<<<nb, 1024>>>(N);
    k_scan3<<<(N + 255) / 256, 256>>>(nb, N, M);
    k_scatter<<<(M + 255) / 256, 256>>>(srcp, dstp, M);

    k_gemm1<<<(N + 3) / 4, 128>>>(x, as1, ad1, N);
    k_agg<<<N, 128>>>(b1, 1, N);

    k_gemm2<<<(N + G2N - 1) / G2N, 128>>>(as2, ad2, N);
    k_agg<<<N, 128>>>(b2, 0, N);

    k_pab<<<(N + 15) / 16, 256>>>(dw1, N);
    k_dec<<<1184, 256>>>(ei, eattr, dw1, db1, db2, dw3, db3, out, M);
}

// round 11
// speedup vs baseline: 1.7332x; 1.0078x over previous
#include <cuda_runtime.h>
#include <cuda_fp16.h>
#include <math.h>

#define NMAX 100000
#define EMAX 1600000
#define HEADS 4
#define HID 32
#define F1 128
#define IN_NODE 12
#define IN_GLB 11
#define IN1 23
#define EDGE_DIM 5
#define DEC_IN 69
#define DEC_H1 64
#define DEC_H2 32
#define DEC_OUT 4

typedef unsigned long long ull;

__device__ __align__(16) __half g_gh[NMAX * F1];    // fp16 gather payload
__device__ float g_h1[NMAX * F1];
__device__ float g_h2[NMAX * HID];
__device__ __align__(16) __half g_pah[NMAX * DEC_H1];
__device__ __align__(16) __half g_pbh[NMAX * DEC_H1];
__device__ __align__(16) float g_als[NMAX * HEADS];
__device__ __align__(16) float g_ald[NMAX * HEADS];
__device__ int   g_cnt[NMAX];
__device__ int   g_off[NMAX + 1];
__device__ int   g_cur[NMAX];
__device__ int   g_srcs[EMAX];
__device__ int   g_bsum[128];
__device__ float g_t1[F1];
__device__ float g_w1tt[IN_NODE * F1];
__device__ float g_w2t[DEC_H1 * DEC_H2];
__device__ __align__(16) ull g_w2p[F1 * F1];

__device__ __forceinline__ float lrelu02(float x) { return x > 0.f ? x : 0.2f * x; }
__device__ __forceinline__ float eluf(float x)    { return x > 0.f ? x : expm1f(x); }

__device__ __forceinline__ ull pk2(float lo, float hi) {
    ull r;
    asm("mov.b64 %0, {%1, %2};" : "=l"(r) : "f"(lo), "f"(hi));
    return r;
}
__device__ __forceinline__ void fma2(ull& d, ull a, ull b) {
    asm("fma.rn.f32x2 %0, %1, %2, %0;" : "+l"(d) : "l"(a), "l"(b));
}
__device__ __forceinline__ float2 upk2(ull v) {
    float2 f;
    asm("mov.b64 {%0, %1}, %2;" : "=f"(f.x), "=f"(f.y) : "l"(v));
    return f;
}

// ---------------- prep ------------------------------------------------------
__global__ void k_prep(const float* __restrict__ u, const float* __restrict__ W1,
                       const float* __restrict__ dw2) {
    int tid = threadIdx.x;
    if (tid < F1) {
        float s = 0.f;
        #pragma unroll
        for (int k = 0; k < IN_GLB; k++) s += u[k] * W1[tid * IN1 + IN_NODE + k];
        g_t1[tid] = s;
    }
    for (int i = tid; i < IN_NODE * F1; i += blockDim.x) {
        int k = i >> 7, f = i & 127;
        g_w1tt[i] = W1[f * IN1 + k];
    }
    for (int i = tid; i < DEC_H1 * DEC_H2; i += blockDim.x) {
        int k = i >> 5, o = i & 31;
        g_w2t[i] = dw2[o * DEC_H1 + k];
    }
}

__global__ void k_prep2(const float* __restrict__ W2) {
    int i = blockIdx.x * 256 + threadIdx.x;
    int k = i >> 7, f = i & 127;
    float w = W2[f * F1 + k];
    g_w2p[i] = pk2(w, w);
}

// ---------------- layer-1 node transform + attention logits ----------------
__global__ void k_gemm1(const float* __restrict__ x,
                        const float* __restrict__ asrc, const float* __restrict__ adst,
                        int N) {
    int n0 = blockIdx.x * 4;
    int f = threadIdx.x;
    __shared__ float xs[4][IN_NODE];
    if (f < 4 * IN_NODE) {
        int i = f / IN_NODE, k = f - i * IN_NODE;
        int n = n0 + i;
        xs[i][k] = (n < N) ? __ldcs(&x[n * IN_NODE + k]) : 0.f;
    }
    __syncthreads();
    float acc[4];
    float t = g_t1[f];
    #pragma unroll
    for (int i = 0; i < 4; i++) acc[i] = t;
    #pragma unroll
    for (int k = 0; k < IN_NODE; k++) {
        float w = g_w1tt[k * F1 + f];
        #pragma unroll
        for (int i = 0; i < 4; i++) acc[i] += xs[i][k] * w;
    }
    int h = f >> 5;
    float cas = asrc[f], cad = adst[f];
    #pragma unroll
    for (int i = 0; i < 4; i++) {
        int n = n0 + i;
        if (n >= N) break;
        g_gh[n * F1 + f] = __float2half_rn(acc[i]);
        float vs = acc[i] * cas, vd = acc[i] * cad;
        #pragma unroll
        for (int o = 16; o; o >>= 1) {
            vs += __shfl_xor_sync(0xffffffffu, vs, o);
            vd += __shfl_xor_sync(0xffffffffu, vd, o);
        }
        if ((f & 31) == 0) {
            g_als[n * HEADS + h] = vs;
            g_ald[n * HEADS + h] = vd;
        }
    }
}

// ---------------- layer-2 node transform: 32 nodes/block, 4f x 8n tiles -----
#define G2N 32
#define HSTS 36
__global__ __launch_bounds__(128) void k_gemm2(const float* __restrict__ asrc,
                                               const float* __restrict__ adst,
                                               int N) {
    __shared__ __align__(16) float hst[F1 * HSTS];
    int tid = threadIdx.x;
    int n0 = blockIdx.x * G2N;

    for (int i = tid; i < G2N * (F1 / 4); i += 128) {
        int n = i >> 5, f4 = i & 31;
        float4 hv = make_float4(0.f, 0.f, 0.f, 0.f);
        if (n0 + n < N)
            hv = __ldcs(reinterpret_cast<const float4*>(&g_h1[(size_t)(n0 + n) * F1 + 4 * f4]));
        hst[(4 * f4 + 0) * HSTS + n] = hv.x;
        hst[(4 * f4 + 1) * HSTS + n] = hv.y;
        hst[(4 * f4 + 2) * HSTS + n] = hv.z;
        hst[(4 * f4 + 3) * HSTS + n] = hv.w;
    }
    __syncthreads();

    int fq = tid >> 2, nq = tid & 3;
    int f0 = fq * 4, nn0 = nq * 8;

    ull acc[4][4];
    #pragma unroll
    for (int a = 0; a < 4; a++)
        #pragma unroll
        for (int b = 0; b < 4; b++) acc[a][b] = 0ull;

    #pragma unroll 4
    for (int k = 0; k < F1; k++) {
        ulonglong2 h01 = *reinterpret_cast<const ulonglong2*>(&hst[k * HSTS + nn0]);
        ulonglong2 h23 = *reinterpret_cast<const ulonglong2*>(&hst[k * HSTS + nn0 + 4]);
        const ulonglong2* wp = reinterpret_cast<const ulonglong2*>(&g_w2p[(size_t)k * F1 + f0]);
        ulonglong2 w01 = wp[0];
        ulonglong2 w23 = wp[1];
        fma2(acc[0][0], h01.x, w01.x); fma2(acc[0][1], h01.y, w01.x);
        fma2(acc[0][2], h23.x, w01.x); fma2(acc[0][3], h23.y, w01.x);
        fma2(acc[1][0], h01.x, w01.y); fma2(acc[1][1], h01.y, w01.y);
        fma2(acc[1][2], h23.x, w01.y); fma2(acc[1][3], h23.y, w01.y);
        fma2(acc[2][0], h01.x, w23.x); fma2(acc[2][1], h01.y, w23.x);
        fma2(acc[2][2], h23.x, w23.x); fma2(acc[2][3], h23.y, w23.x);
        fma2(acc[3][0], h01.x, w23.y); fma2(acc[3][1], h01.y, w23.y);
        fma2(acc[3][2], h23.x, w23.y); fma2(acc[3][3], h23.y, w23.y);
    }

    float av[4][8];
    #pragma unroll
    for (int f = 0; f < 4; f++)
        #pragma unroll
        for (int p = 0; p < 4; p++) {
            float2 t = upk2(acc[f][p]);
            av[f][2 * p] = t.x;
            av[f][2 * p + 1] = t.y;
        }

    float4 cas = *reinterpret_cast<const float4*>(&asrc[f0]);
    float4 cad = *reinterpret_cast<const float4*>(&adst[f0]);
    float vs[8], vd[8];
    #pragma unroll
    for (int j = 0; j < 8; j++) {
        int n = n0 + nn0 + j;
        if (n < N) {
            __half2 p0 = __floats2half2_rn(av[0][j], av[1][j]);
            __half2 p1 = __floats2half2_rn(av[2][j], av[3][j]);
            __half2* gp = reinterpret_cast<__half2*>(&g_gh[(size_t)n * F1 + f0]);
            gp[0] = p0;
            gp[1] = p1;
        }
        vs[j] = av[0][j] * cas.x + av[1][j] * cas.y + av[2][j] * cas.z + av[3][j] * cas.w;
        vd[j] = av[0][j] * cad.x + av[1][j] * cad.y + av[2][j] * cad.z + av[3][j] * cad.w;
    }
    #pragma unroll
    for (int j = 0; j < 8; j++) {
        #pragma unroll
        for (int m = 4; m <= 16; m <<= 1) {
            vs[j] += __shfl_xor_sync(0xffffffffu, vs[j], m);
            vd[j] += __shfl_xor_sync(0xffffffffu, vd[j], m);
        }
    }
    if ((tid & 28) == 0) {
        int h = tid >> 5;
        #pragma unroll
        for (int j = 0; j < 8; j++) {
            int n = n0 + nn0 + j;
            if (n < N) {
                g_als[n * HEADS + h] = vs[j];
                g_ald[n * HEADS + h] = vd[j];
            }
        }
    }
}

// ---------------- CSR build --------------------------------------------------
__global__ void k_zero(int N) {
    int i = blockIdx.x * blockDim.x + threadIdx.x;
    if (i < N) g_cnt[i] = 0;
}
__global__ void k_hist(const int* __restrict__ dst, int M) {
    int e = blockIdx.x * blockDim.x + threadIdx.x;
    if (e < M) atomicAdd(&g_cnt[__ldcs(&dst[e])], 1);
}
__global__ void k_scan1(int N) {
    __shared__ int sh[1024];
    int tid = threadIdx.x;
    int i = blockIdx.x * 1024 + tid;
    int v = (i < N) ? g_cnt[i] : 0;
    sh[tid] = v;
    __syncthreads();
    for (int o = 1; o < 1024; o <<= 1) {
        int t = (tid >= o) ? sh[tid - o] : 0;
        __syncthreads();
        sh[tid] += t;
        __syncthreads();
    }
    if (i < N) g_off[i] = sh[tid] - v;
    if (tid == 1023) g_bsum[blockIdx.x] = sh[1023];
}
__global__ void k_scan3(int nb, int N, int M) {
    __shared__ int sh[128];
    int tid = threadIdx.x;
    if (tid < 128) {
        int v = (tid < nb) ? g_bsum[tid] : 0;
        sh[tid] = v;
    }
    __syncthreads();
    if (tid < 128) {
        for (int o = 1; o < 128; o <<= 1) {
            int t = (tid >= o) ? sh[tid - o] : 0;
            __syncthreads();
            sh[tid] += t;
            __syncthreads();
        }
    } else {
        for (int o = 1; o < 128; o <<= 1) { __syncthreads(); __syncthreads(); }
    }
    int i = blockIdx.x * blockDim.x + tid;
    if (i < N) {
        int blk = i >> 10;
        int ex = (blk == 0) ? 0 : sh[blk - 1];
        int v = g_off[i] + ex;
        g_off[i] = v;
        g_cur[i] = v;
    }
    if (i == 0) g_off[N] = M;
}
__global__ void k_scatter(const int* __restrict__ src, const int* __restrict__ dst, int M) {
    int e = blockIdx.x * blockDim.x + threadIdx.x;
    if (e < M) {
        int d = __ldcs(&dst[e]);
        int p = atomicAdd(&g_cur[d], 1);
        g_srcs[p] = __ldcs(&src[e]);
    }
}

// ---------------- GAT aggregation (4 warps/node; fp16 gathers) --------------
__global__ void k_agg(const float* __restrict__ bias, int concat, int N) {
    int n = blockIdx.x;
    if (n >= N) return;
    int h = threadIdx.x >> 5;
    int lane = threadIdx.x & 31;
    int beg = g_off[n], end = g_off[n + 1];

    float ad = g_ald[n * HEADS + h];
    float ws = __expf(lrelu02(g_als[n * HEADS + h] + ad));

    const __half* gg = g_gh + (h << 5) + lane;
    float acc = ws * __half2float(gg[(size_t)n * F1]);
    float psum = 0.f;
    for (int base = beg; base < end; base += 32) {
        int j = base + lane;
        float w = 0.f;
        int s = 0;
        if (j < end) {
            s = g_srcs[j];
            w = __expf(lrelu02(g_als[s * HEADS + h] + ad));
            psum += w;
        }
        int lim = min(32, end - base);
        int kk = 0;
        for (; kk + 4 <= lim; kk += 4) {
            float w0 = __shfl_sync(0xffffffffu, w, kk);
            float w1 = __shfl_sync(0xffffffffu, w, kk + 1);
            float w2 = __shfl_sync(0xffffffffu, w, kk + 2);
            float w3 = __shfl_sync(0xffffffffu, w, kk + 3);
            int s0 = __shfl_sync(0xffffffffu, s, kk);
            int s1 = __shfl_sync(0xffffffffu, s, kk + 1);
            int s2 = __shfl_sync(0xffffffffu, s, kk + 2);
            int s3 = __shfl_sync(0xffffffffu, s, kk + 3);
            float v0 = __half2float(gg[(size_t)s0 * F1]);
            float v1 = __half2float(gg[(size_t)s1 * F1]);
            float v2 = __half2float(gg[(size_t)s2 * F1]);
            float v3 = __half2float(gg[(size_t)s3 * F1]);
            acc += w0 * v0;
            acc += w1 * v1;
            acc += w2 * v2;
            acc += w3 * v3;
        }
        for (; kk < lim; kk++) {
            float wk = __shfl_sync(0xffffffffu, w, kk);
            int sk = __shfl_sync(0xffffffffu, s, kk);
            acc += wk * __half2float(gg[(size_t)sk * F1]);
        }
    }
    #pragma unroll
    for (int o = 16; o; o >>= 1) psum += __shfl_xor_sync(0xffffffffu, psum, o);
    float v = acc / (psum + ws);

    if (concat) {
        v += bias[(h << 5) + lane];
        __stcs(&g_h1[n * F1 + (h << 5) + lane], eluf(v));
    } else {
        __shared__ float sm[F1];
        sm[(h << 5) + lane] = v;
        __syncthreads();
        if (h == 0) {
            float t = (sm[lane] + sm[32 + lane] + sm[64 + lane] + sm[96 + lane]) * 0.25f
                      + bias[lane];
            g_h2[n * HID + lane] = eluf(t);
        }
    }
}

// ---------------- decoder precompute: pa/pb (fp16 out) ----------------------
__global__ __launch_bounds__(256) void k_pab(const float* __restrict__ dw1, int N) {
    __shared__ float sdw[64 * 65];
    __shared__ float sh2[16 * 32];
    int tid = threadIdx.x;
    for (int i = tid; i < 64 * 64; i += 256) {
        int o = i >> 6, k = i & 63;
        sdw[o * 65 + k] = dw1[o * DEC_IN + k];
    }
    int n0 = blockIdx.x * 16;
    for (int i = tid; i < 16 * 32; i += 256) {
        int nl = i >> 5, k = i & 31;
        int n = n0 + nl;
        sh2[i] = (n < N) ? g_h2[n * HID + k] : 0.f;
    }
    __syncthreads();
    int o = tid & 63, ng = tid >> 6;
    float pa[4] = {0.f, 0.f, 0.f, 0.f}, pb[4] = {0.f, 0.f, 0.f, 0.f};
    #pragma unroll
    for (int k = 0; k < 32; k++) {
        float wa = sdw[o * 65 + k];
        float wb = sdw[o * 65 + 32 + k];
        #pragma unroll
        for (int j = 0; j < 4; j++) {
            float hv = sh2[(ng * 4 + j) * 32 + k];
            pa[j] += wa * hv;
            pb[j] += wb * hv;
        }
    }
    #pragma unroll
    for (int j = 0; j < 4; j++) {
        int n = n0 + ng * 4 + j;
        if (n < N) {
            g_pah[n * 64 + o] = __float2half_rn(pa[j]);
            g_pbh[n * 64 + o] = __float2half_rn(pb[j]);
        }
    }
}

// ---------------- decoder: 64-edge tiles; GEMM2 4e x 4o ---------------------
#define TB 64
#define ZS (TB + 4)
__global__ __launch_bounds__(256) void k_dec(
    const int* __restrict__ ei, const float* __restrict__ eattr,
    const float* __restrict__ dw1, const float* __restrict__ db1,
    const float* __restrict__ db2, const float* __restrict__ dw3,
    const float* __restrict__ db3, float* __restrict__ out, int M) {
    __shared__ __align__(16) ull sw2p[DEC_H1 * DEC_H2];
    __shared__ float sw3[DEC_H2 * DEC_OUT];
    __shared__ float sb2[DEC_H2];
    __shared__ float sb3[DEC_OUT];
    __shared__ float sw1c[EDGE_DIM * 64];
    __shared__ float sdb1[64];
    __shared__ int ssrc[TB], sdst[TB];
    __shared__ float eat[TB * EDGE_DIM];
    __shared__ __align__(16) float z1t[DEC_H1 * ZS];
    __shared__ __align__(16) float z2t[DEC_H2 * ZS];
    int tid = threadIdx.x;

    for (int i = tid; i < DEC_H1 * DEC_H2; i += 256) {
        float w = g_w2t[i];
        sw2p[i] = pk2(w, w);
    }
    if (tid < 128) sw3[tid] = dw3[tid];
    if (tid < 64)  sdb1[tid] = db1[tid];
    if (tid < 32)  sb2[tid] = db2[tid];
    if (tid < 4)   sb3[tid] = db3[tid];
    for (int i = tid; i < EDGE_DIM * 64; i += 256) {
        int k = i >> 6, o = i & 63;
        sw1c[i] = dw1[o * DEC_IN + 64 + k];
    }

    const int* srcp = ei;
    const int* dstp = ei + M;
    int ntiles = (M + TB - 1) / TB;
    int eg = tid & 15, og = tid >> 4;
    int e0 = eg * 4, o0 = og * 4;

    for (int tile = blockIdx.x; tile < ntiles; tile += gridDim.x) {
        int eb = tile * TB;
        int nE = min(TB, M - eb);
        __syncthreads();
        if (tid < TB) {
            ssrc[tid] = (tid < nE) ? __ldcs(&srcp[eb + tid]) : 0;
            sdst[tid] = (tid < nE) ? __ldcs(&dstp[eb + tid]) : 0;
        }
        for (int i = tid; i < TB * EDGE_DIM; i += 256) {
            int gi = eb * EDGE_DIM + i;
            eat[i] = (gi < M * EDGE_DIM) ? __ldcs(&eattr[gi]) : 0.f;
        }
        __syncthreads();

        for (int i = tid; i < TB * 64; i += 256) {
            int e = i >> 6, o = i & 63;
            float v = __half2float(g_pah[(size_t)ssrc[e] * 64 + o])
                    + __half2float(g_pbh[(size_t)sdst[e] * 64 + o])
                    + sdb1[o];
            #pragma unroll
            for (int k = 0; k < EDGE_DIM; k++) v += sw1c[k * 64 + o] * eat[e * EDGE_DIM + k];
            z1t[o * ZS + e] = fmaxf(v, 0.f);
        }
        __syncthreads();

        if (tid < 128) {
            ull acc[4][2];
            #pragma unroll
            for (int a = 0; a < 4; a++) { acc[a][0] = 0ull; acc[a][1] = 0ull; }
            #pragma unroll 8
            for (int k = 0; k < DEC_H1; k++) {
                ulonglong2 zp = *reinterpret_cast<const ulonglong2*>(&z1t[k * ZS + e0]);
                ulonglong2 w01 = *reinterpret_cast<const ulonglong2*>(&sw2p[k * DEC_H2 + o0]);
                ulonglong2 w23 = *reinterpret_cast<const ulonglong2*>(&sw2p[k * DEC_H2 + o0 + 2]);
                fma2(acc[0][0], zp.x, w01.x); fma2(acc[0][1], zp.y, w01.x);
                fma2(acc[1][0], zp.x, w01.y); fma2(acc[1][1], zp.y, w01.y);
                fma2(acc[2][0], zp.x, w23.x); fma2(acc[2][1], zp.y, w23.x);
                fma2(acc[3][0], zp.x, w23.y); fma2(acc[3][1], zp.y, w23.y);
            }
            #pragma unroll
            for (int o = 0; o < 4; o++) {
                float b = sb2[o0 + o];
                float2 t0 = upk2(acc[o][0]);
                float2 t1 = upk2(acc[o][1]);
                float4 ov = make_float4(fmaxf(t0.x + b, 0.f), fmaxf(t0.y + b, 0.f),
                                        fmaxf(t1.x + b, 0.f), fmaxf(t1.y + b, 0.f));
                *reinterpret_cast<float4*>(&z2t[(o0 + o) * ZS + e0]) = ov;
            }
        }
        __syncthreads();

        {
            int e = tid & 63, o = tid >> 6;
            float acc = sb3[o];
            #pragma unroll
            for (int k = 0; k < DEC_H2; k++) acc += z2t[k * ZS + e] * sw3[o * DEC_H2 + k];
            if (e < nE) __stcs(&out[(eb + e) * DEC_OUT + o], acc);
        }
    }
}

// ---------------- launch -----------------------------------------------------
extern "C" void kernel_launch(void* const* d_in, const int* in_sizes, int n_in,
                              void* d_out, int out_size) {
    const float* x     = (const float*)d_in[0];
    const int*   ei    = (const int*)d_in[1];
    const float* eattr = (const float*)d_in[2];
    const float* u     = (const float*)d_in[3];
    const float* W1    = (const float*)d_in[4];
    const float* as1   = (const float*)d_in[5];
    const float* ad1   = (const float*)d_in[6];
    const float* b1    = (const float*)d_in[7];
    const float* W2    = (const float*)d_in[8];
    const float* as2   = (const float*)d_in[9];
    const float* ad2   = (const float*)d_in[10];
    const float* b2    = (const float*)d_in[11];
    const float* dw1   = (const float*)d_in[12];
    const float* db1   = (const float*)d_in[13];
    const float* dw2   = (const float*)d_in[14];
    const float* db2   = (const float*)d_in[15];
    const float* dw3   = (const float*)d_in[16];
    const float* db3   = (const float*)d_in[17];
    float* out = (float*)d_out;

    int N = in_sizes[0] / IN_NODE;
    int M = in_sizes[1] / 2;
    if (N > NMAX || M > EMAX || N <= 0 || M <= 0) return;

    const int* srcp = ei;
    const int* dstp = ei + M;
    int nb = (N + 1023) / 1024;

    k_zero<<<(N + 255) / 256, 256>>>(N);
    k_prep<<<1, 256>>>(u, W1, dw2);
    k_prep2<<<64, 256>>>(W2);
    k_hist<<<(M + 255) / 256, 256>>>(dstp, M);
    k_scan1<<<nb, 1024>>>(N);
    k_scan3<<<(N + 255) / 256, 256>>>(nb, N, M);
    k_scatter<<<(M + 255) / 256, 256>>>(srcp, dstp, M);

    k_gemm1<<<(N + 3) / 4, 128>>>(x, as1, ad1, N);
    k_agg<<<N, 128>>>(b1, 1, N);

    k_gemm2<<<(N + G2N - 1) / G2N, 128>>>(as2, ad2, N);
    k_agg<<<N, 128>>>(b2, 0, N);

    k_pab<<<(N + 15) / 16, 256>>>(dw1, N);
    k_dec<<<1184, 256>>>(ei, eattr, dw1, db1, db2, dw3, db3, out, M);
}